// round 2
// baseline (speedup 1.0000x reference)
#include <cuda_runtime.h>
#include <cuda_fp16.h>
#include <cstdint>
#include <cstddef>

#define HW 4096
#define CIN 1088
#define CMID 136

// ---------------- scratch (device globals; no allocs allowed) ----------------
__device__ float  g_feat[2][2][(size_t)CMID * HW];       // [a/b][n][c*HW+p]
__device__ float  g_E[2][(size_t)HW * HW];               // energy (already *100)
__device__ __half g_corr_h[2][2][(size_t)HW * HW];       // [ab/ba][n]
__device__ __half g_raw_h[2][2][(size_t)CIN * HW];       // [a/b][n]

// ---------------- PTX helpers ----------------
__device__ __forceinline__ uint32_t smaddr(const void* p) {
    return (uint32_t)__cvta_generic_to_shared(p);
}
__device__ __forceinline__ void ldsm4(uint32_t r[4], const void* p) {
    asm volatile("ldmatrix.sync.aligned.m8n8.x4.shared.b16 {%0,%1,%2,%3}, [%4];\n"
                 : "=r"(r[0]), "=r"(r[1]), "=r"(r[2]), "=r"(r[3]) : "r"(smaddr(p)));
}
__device__ __forceinline__ void ldsm4t(uint32_t r[4], const void* p) {
    asm volatile("ldmatrix.sync.aligned.m8n8.x4.trans.shared.b16 {%0,%1,%2,%3}, [%4];\n"
                 : "=r"(r[0]), "=r"(r[1]), "=r"(r[2]), "=r"(r[3]) : "r"(smaddr(p)));
}
__device__ __forceinline__ void mma16816(float* d, const uint32_t* a, const uint32_t* b) {
    asm volatile("mma.sync.aligned.m16n8k16.row.col.f32.f16.f16.f32 "
                 "{%0,%1,%2,%3}, {%4,%5,%6,%7}, {%8,%9}, {%0,%1,%2,%3};\n"
                 : "+f"(d[0]), "+f"(d[1]), "+f"(d[2]), "+f"(d[3])
                 : "r"(a[0]), "r"(a[1]), "r"(a[2]), "r"(a[3]), "r"(b[0]), "r"(b[1]));
}
__device__ __forceinline__ void cpa16(const void* sm, const void* g, int bytes) {
    asm volatile("cp.async.cg.shared.global [%0], [%1], 16, %2;\n"
                 :: "r"(smaddr(sm)), "l"(g), "r"(bytes));
}
#define CP_COMMIT() asm volatile("cp.async.commit_group;\n" ::: "memory")
#define CP_WAIT(n)  asm volatile("cp.async.wait_group %0;\n" :: "n"(n) : "memory")

// ---------------- K1: 1x1 conv  Y[136,4096] = W@X + b ----------------
__global__ void conv_kernel(const float* __restrict__ fa, const float* __restrict__ fb,
                            const float* __restrict__ Wa, const float* __restrict__ ba,
                            const float* __restrict__ Wb, const float* __restrict__ bb) {
    const int t = blockIdx.z, n = blockIdx.y;
    const float* __restrict__ X = (t == 0 ? fa : fb) + (size_t)n * CIN * HW;
    const float* __restrict__ W = (t == 0 ? Wa : Wb);
    const float* __restrict__ bias = (t == 0 ? ba : bb);

    __shared__ float Wsh[CMID][33];
    __shared__ __align__(16) float Xsh[32][64];

    const int tx = threadIdx.x & 15, ty = threadIdx.x >> 4;
    const int p0 = blockIdx.x * 64;

    float acc[17][4];
#pragma unroll
    for (int i = 0; i < 17; ++i)
#pragma unroll
        for (int j = 0; j < 4; ++j) acc[i][j] = 0.f;

    for (int c0 = 0; c0 < CIN; c0 += 32) {
        for (int id = threadIdx.x; id < CMID * 32; id += 128) {
            int o = id >> 5, k = id & 31;
            Wsh[o][k] = W[(size_t)o * CIN + c0 + k];
        }
        for (int id = threadIdx.x; id < 32 * 64; id += 128) {
            int k = id >> 6, j = id & 63;
            Xsh[k][j] = X[(size_t)(c0 + k) * HW + p0 + j];
        }
        __syncthreads();
#pragma unroll
        for (int k = 0; k < 32; ++k) {
            float xv[4];
            *(float4*)xv = *(const float4*)&Xsh[k][tx * 4];
#pragma unroll
            for (int i = 0; i < 17; ++i) {
                float wv = Wsh[ty + 8 * i][k];
                acc[i][0] += wv * xv[0]; acc[i][1] += wv * xv[1];
                acc[i][2] += wv * xv[2]; acc[i][3] += wv * xv[3];
            }
        }
        __syncthreads();
    }
    float* __restrict__ Y = g_feat[t][n];
#pragma unroll
    for (int i = 0; i < 17; ++i) {
        int o = ty + 8 * i;
        float bv = bias[o];
        float4 r = make_float4(acc[i][0] + bv, acc[i][1] + bv, acc[i][2] + bv, acc[i][3] + bv);
        *(float4*)&Y[(size_t)o * HW + p0 + tx * 4] = r;
    }
}

// ---------------- K2: InstanceNorm + LeakyReLU + mean-center ----------------
__global__ void inorm_kernel() {
    const int c = blockIdx.x, n = blockIdx.y, t = blockIdx.z;
    float* __restrict__ Y = &g_feat[t][n][(size_t)c * HW];
    __shared__ float sd[HW];
    __shared__ float r1[256], r2[256];
    const int tid = threadIdx.x;

    float s = 0.f, q = 0.f;
    for (int i = tid; i < HW; i += 256) { float v = Y[i]; sd[i] = v; s += v; q += v * v; }
    r1[tid] = s; r2[tid] = q; __syncthreads();
    for (int st = 128; st > 0; st >>= 1) {
        if (tid < st) { r1[tid] += r1[tid + st]; r2[tid] += r2[tid + st]; }
        __syncthreads();
    }
    const float mean = r1[0] * (1.f / HW);
    const float var  = r2[0] * (1.f / HW) - mean * mean;
    const float inv  = rsqrtf(var + 1e-5f);
    __syncthreads();

    float s2 = 0.f;
    for (int i = tid; i < HW; i += 256) {
        float v = (sd[i] - mean) * inv;
        v = (v >= 0.f) ? v : 0.2f * v;
        sd[i] = v; s2 += v;
    }
    r1[tid] = s2; __syncthreads();
    for (int st = 128; st > 0; st >>= 1) {
        if (tid < st) r1[tid] += r1[tid + st];
        __syncthreads();
    }
    const float mean2 = r1[0] * (1.f / HW);
    for (int i = tid; i < HW; i += 256) Y[i] = sd[i] - mean2;
}

// ---------------- K3: L2-normalize channel vector per position ----------------
__global__ void l2norm_kernel() {
    const int p = blockIdx.x * 256 + threadIdx.x;
    const int n = blockIdx.y, t = blockIdx.z;
    float* __restrict__ F = g_feat[t][n];
    float q = 0.f;
    for (int c = 0; c < CMID; ++c) { float v = F[(size_t)c * HW + p]; q += v * v; }
    const float inv = rsqrtf(q);
    for (int c = 0; c < CMID; ++c) F[(size_t)c * HW + p] *= inv;
}

// ---------------- K4: energy SGEMM  E[k,l] = 100 * <fbn[:,k], fan[:,l]> ----------------
__global__ void energy_kernel() {
    const int n = blockIdx.z;
    const float* __restrict__ A = g_feat[1][n];   // fbn -> k
    const float* __restrict__ B = g_feat[0][n];   // fan -> l
    float* __restrict__ E = g_E[n];
    __shared__ __align__(16) float Ash[8][128];
    __shared__ __align__(16) float Bsh[8][128];
    const int tid = threadIdx.x;
    const int tx = tid & 15, ty = tid >> 4;
    const int m0 = blockIdx.y * 128, n0 = blockIdx.x * 128;
    const int lc = tid >> 5, j4 = (tid & 31) * 4;

    float acc[8][8];
#pragma unroll
    for (int i = 0; i < 8; ++i)
#pragma unroll
        for (int j = 0; j < 8; ++j) acc[i][j] = 0.f;

    for (int c0 = 0; c0 < CMID; c0 += 8) {
        *(float4*)&Ash[lc][j4] = *(const float4*)&A[(size_t)(c0 + lc) * HW + m0 + j4];
        *(float4*)&Bsh[lc][j4] = *(const float4*)&B[(size_t)(c0 + lc) * HW + n0 + j4];
        __syncthreads();
#pragma unroll
        for (int c = 0; c < 8; ++c) {
            float a[8], b[8];
            *(float4*)&a[0] = *(const float4*)&Ash[c][ty * 8];
            *(float4*)&a[4] = *(const float4*)&Ash[c][ty * 8 + 4];
            *(float4*)&b[0] = *(const float4*)&Bsh[c][tx * 8];
            *(float4*)&b[4] = *(const float4*)&Bsh[c][tx * 8 + 4];
#pragma unroll
            for (int i = 0; i < 8; ++i)
#pragma unroll
                for (int j = 0; j < 8; ++j) acc[i][j] += a[i] * b[j];
        }
        __syncthreads();
    }
#pragma unroll
    for (int i = 0; i < 8; ++i) {
        size_t row = (size_t)(m0 + ty * 8 + i) * HW + n0 + tx * 8;
        *(float4*)&E[row]     = make_float4(acc[i][0]*100.f, acc[i][1]*100.f, acc[i][2]*100.f, acc[i][3]*100.f);
        *(float4*)&E[row + 4] = make_float4(acc[i][4]*100.f, acc[i][5]*100.f, acc[i][6]*100.f, acc[i][7]*100.f);
    }
}

// ---------------- K5a: row softmax -> corr_ab (fp32 out + fp16 scratch) ----------------
__global__ void rowsoftmax_kernel(float* __restrict__ out_ab) {
    const int row = blockIdx.x, n = blockIdx.y;
    const float* __restrict__ e = &g_E[n][(size_t)row * HW];
    const int tid = threadIdx.x;
    float v[16];
    float m = -1e30f;
#pragma unroll
    for (int i = 0; i < 16; ++i) { v[i] = e[tid + i * 256]; m = fmaxf(m, v[i]); }
    __shared__ float red[256];
    red[tid] = m; __syncthreads();
    for (int st = 128; st > 0; st >>= 1) {
        if (tid < st) red[tid] = fmaxf(red[tid], red[tid + st]);
        __syncthreads();
    }
    m = red[0]; __syncthreads();
    float s = 0.f;
#pragma unroll
    for (int i = 0; i < 16; ++i) { v[i] = __expf(v[i] - m); s += v[i]; }
    red[tid] = s; __syncthreads();
    for (int st = 128; st > 0; st >>= 1) {
        if (tid < st) red[tid] += red[tid + st];
        __syncthreads();
    }
    const float inv = 1.0f / red[0];
    float* __restrict__ o = out_ab + ((size_t)n * HW + row) * HW;
    __half* __restrict__ oh = &g_corr_h[0][n][(size_t)row * HW];
#pragma unroll
    for (int i = 0; i < 16; ++i) {
        float p = v[i] * inv;
        o[tid + i * 256]  = p;
        oh[tid + i * 256] = __float2half_rn(p);
    }
}

// ---------------- K5b: column softmax of E -> corr_ba (transposed write) ----------------
__global__ void colsoftmax_kernel(float* __restrict__ out_ba) {
    const int n = blockIdx.y;
    const int k0 = blockIdx.x * 64;
    const float* __restrict__ E = g_E[n];
    const int tid = threadIdx.x;
    const int tx = tid & 63, ty = tid >> 6;
    __shared__ float sm_m[4][64], sm_s[4][64];

    float m = -1e30f;
    for (int l = ty; l < HW; l += 4) m = fmaxf(m, E[(size_t)l * HW + k0 + tx]);
    sm_m[ty][tx] = m; __syncthreads();
    m = fmaxf(fmaxf(sm_m[0][tx], sm_m[1][tx]), fmaxf(sm_m[2][tx], sm_m[3][tx]));

    float s = 0.f;
    for (int l = ty; l < HW; l += 4) s += __expf(E[(size_t)l * HW + k0 + tx] - m);
    sm_s[ty][tx] = s; __syncthreads();
    const float invS = 1.0f / (sm_s[0][tx] + sm_s[1][tx] + sm_s[2][tx] + sm_s[3][tx]);

    __shared__ float tile[64][65];
    float* __restrict__ ob = out_ba + (size_t)n * HW * HW;
    __half* __restrict__ oh = g_corr_h[1][n];
    for (int l0 = 0; l0 < HW; l0 += 64) {
        __syncthreads();
#pragma unroll
        for (int i = 0; i < 16; ++i) {
            int ll = ty * 16 + i;
            tile[tx][ll] = __expf(E[(size_t)(l0 + ll) * HW + k0 + tx] - m) * invS;
        }
        __syncthreads();
#pragma unroll
        for (int i = 0; i < 16; ++i) {
            int kk = ty * 16 + i;
            float p = tile[kk][tx];
            size_t off = (size_t)(k0 + kk) * HW + l0 + tx;
            ob[off] = p;
            oh[off] = __float2half_rn(p);
        }
    }
}

// ---------------- K6: raw -> fp16 ----------------
__global__ void tohalf_kernel(const float* __restrict__ a_raw, const float* __restrict__ b_raw) {
    const int t = blockIdx.y;
    const float* __restrict__ src = (t == 0 ? a_raw : b_raw);
    __half* __restrict__ dst = &g_raw_h[t][0][0];
    size_t i = ((size_t)blockIdx.x * 256 + threadIdx.x) * 4;
    float4 v = *(const float4*)&src[i];
    __half2* d2 = (__half2*)&dst[i];
    d2[0] = __floats2half2_rn(v.x, v.y);
    d2[1] = __floats2half2_rn(v.z, v.w);
}

// ---------------- K7: warp matmul  C[1088,4096] = raw_h @ corr_h ----------------
__global__ void warp_gemm_kernel(float* __restrict__ out) {
    const int z = blockIdx.z;
    const int dir = z >> 1;     // 0: a_warp (uses corr_ba), 1: b_warp (uses corr_ab)
    const int n = z & 1;
    const __half* __restrict__ A = g_raw_h[dir][n];
    const __half* __restrict__ B = g_corr_h[dir ^ 1][n];
    float* __restrict__ C = out + (size_t)4 * HW * HW
                                + (size_t)dir * 2 * CIN * HW + (size_t)n * CIN * HW;
    const int m0 = blockIdx.y * 128, n0 = blockIdx.x * 128;
    const int tid = threadIdx.x, lane = tid & 31, warp = tid >> 5;
    const int wm = warp & 3, wn = warp >> 2;

    __shared__ __align__(16) __half As[2][128][40];
    __shared__ __align__(16) __half Bs[2][32][136];

    float acc[2][8][4];
#pragma unroll
    for (int i = 0; i < 2; ++i)
#pragma unroll
        for (int j = 0; j < 8; ++j)
#pragma unroll
            for (int k = 0; k < 4; ++k) acc[i][j][k] = 0.f;

    auto loadA = [&](int s, int k0) {
#pragma unroll
        for (int i = 0; i < 2; ++i) {
            int c = tid + i * 256;
            int row = c >> 2, cc = (c & 3) * 8;
            int gr = m0 + row;
            int ok = gr < CIN;
            cpa16(&As[s][row][cc], &A[(size_t)(ok ? gr : 0) * HW + k0 + cc], ok ? 16 : 0);
        }
    };
    auto loadB = [&](int s, int k0) {
#pragma unroll
        for (int i = 0; i < 2; ++i) {
            int c = tid + i * 256;
            int row = c >> 4, cc = (c & 15) * 8;
            cpa16(&Bs[s][row][cc], &B[(size_t)(k0 + row) * HW + n0 + cc], 16);
        }
    };

    loadA(0, 0); loadB(0, 0); CP_COMMIT();

    for (int kt = 0; kt < 128; ++kt) {
        const int s = kt & 1;
        if (kt + 1 < 128) {
            loadA(s ^ 1, (kt + 1) * 32); loadB(s ^ 1, (kt + 1) * 32);
            CP_COMMIT(); CP_WAIT(1);
        } else {
            CP_WAIT(0);
        }
        __syncthreads();
        const int r16 = lane & 15, c8 = (lane >> 4) << 3;
#pragma unroll
        for (int ks = 0; ks < 32; ks += 16) {
            uint32_t a[2][4], b[4][4];
#pragma unroll
            for (int mi = 0; mi < 2; ++mi)
                ldsm4(a[mi], &As[s][wm * 32 + mi * 16 + r16][ks + c8]);
#pragma unroll
            for (int nj = 0; nj < 4; ++nj)
                ldsm4t(b[nj], &Bs[s][ks + r16][wn * 64 + nj * 16 + c8]);
#pragma unroll
            for (int mi = 0; mi < 2; ++mi)
#pragma unroll
                for (int nj = 0; nj < 4; ++nj) {
                    mma16816(acc[mi][nj * 2],     a[mi], &b[nj][0]);
                    mma16816(acc[mi][nj * 2 + 1], a[mi], &b[nj][2]);
                }
        }
        __syncthreads();
    }

    const int ln4 = lane >> 2, lc2 = (lane & 3) * 2;
#pragma unroll
    for (int mi = 0; mi < 2; ++mi)
#pragma unroll
        for (int nj = 0; nj < 8; ++nj) {
            int col = n0 + wn * 64 + nj * 8 + lc2;
            int r0 = m0 + wm * 32 + mi * 16 + ln4;
            if (r0 < CIN)
                *(float2*)&C[(size_t)r0 * HW + col] = make_float2(acc[mi][nj][0], acc[mi][nj][1]);
            if (r0 + 8 < CIN)
                *(float2*)&C[(size_t)(r0 + 8) * HW + col] = make_float2(acc[mi][nj][2], acc[mi][nj][3]);
        }
}

// ---------------- launch ----------------
extern "C" void kernel_launch(void* const* d_in, const int* in_sizes, int n_in,
                              void* d_out, int out_size) {
    const float* fa    = (const float*)d_in[0];
    const float* fb    = (const float*)d_in[1];
    const float* a_raw = (const float*)d_in[2];
    const float* b_raw = (const float*)d_in[3];
    const float* Wa    = (const float*)d_in[4];
    const float* ba    = (const float*)d_in[5];
    const float* Wb    = (const float*)d_in[6];
    const float* bb    = (const float*)d_in[7];
    float* out = (float*)d_out;

    conv_kernel<<<dim3(64, 2, 2), 128>>>(fa, fb, Wa, ba, Wb, bb);
    inorm_kernel<<<dim3(CMID, 2, 2), 256>>>();
    l2norm_kernel<<<dim3(HW / 256, 2, 2), 256>>>();
    energy_kernel<<<dim3(32, 32, 2), 256>>>();
    tohalf_kernel<<<dim3(8704, 2), 256>>>(a_raw, b_raw);
    rowsoftmax_kernel<<<dim3(HW, 2), 256>>>(out);
    colsoftmax_kernel<<<dim3(64, 2), 256>>>(out + (size_t)2 * HW * HW);
    warp_gemm_kernel<<<dim3(32, 9, 4), 256>>>(out);
}